// round 13
// baseline (speedup 1.0000x reference)
#include <cuda_runtime.h>
#include <cstdint>

#define N_NODES 100000
#define N_EDGES 1600000
#define IN_DIM  128
#define HID     64
#define ROW_BYTES (HID * 4)   // 256
#define CONVOUT 124   // 2 * 62
#define SCAN_B  1024
#define NSCANB  ((N_NODES + SCAN_B - 1) / SCAN_B)   // 98

typedef unsigned long long ull;

// ---------------- packed f32x2 helpers (Blackwell FFMA2/FADD2) -----------------
__device__ __forceinline__ ull pack2(float x, float y) {
    ull r;
    asm("mov.b64 %0, {%1, %2};" : "=l"(r) : "f"(x), "f"(y));
    return r;
}
__device__ __forceinline__ void unpack2(ull v, float& x, float& y) {
    asm("mov.b64 {%0, %1}, %2;" : "=f"(x), "=f"(y) : "l"(v));
}
__device__ __forceinline__ void fma2(ull& d, ull a, ull b) {
    asm("fma.rn.f32x2 %0, %1, %2, %0;" : "+l"(d) : "l"(a), "l"(b));
}
__device__ __forceinline__ void add2(ull& d, ull a) {
    asm("add.rn.f32x2 %0, %0, %1;" : "+l"(d) : "l"(a));
}

// ---------------- scratch (static device globals; zero at module load) ---------
__device__ float g_t   [N_NODES * HID];   // (feat@w1)*norm
__device__ float g_h1  [N_NODES * HID];   // dropout(relu(agg*norm))*norm
__device__ float g_agg2[N_NODES * HID];   // layer-2 aggregate
__device__ float g_h2  [N_NODES * HID];   // final node features
__device__ int   g_deg [N_NODES];         // zeroed by k_final tail
__device__ int   g_cnt [N_NODES];         // zeroed by k_final tail
__device__ float g_norm[N_NODES];
__device__ int   g_rowptr[N_NODES + 1];
__device__ int   g_bsum[NSCANB];
__device__ int   g_boff[NSCANB];
__device__ int   g_csr[N_EDGES];          // BYTE offsets of src rows, grouped by dst
__device__ ull   g_mask2[N_NODES];        // dropout-2 keep bits (written by gather<0>)
__device__ float g_colsum[HID];           // zeroed in k_gather<0>
__device__ int   g_arrive1;               // deg-phase handshake
__device__ int   g_arrive2;               // bsum handshake
__device__ int   g_arrive3;               // rowptr handshake (pre-fill)
__device__ int   g_flag;                  // boff release

// ---------------- threefry2x32 (20 rounds, JAX-compatible) --------------------
__host__ __device__ __forceinline__ void tf2x32(uint32_t k0, uint32_t k1,
                                                uint32_t& x0, uint32_t& x1) {
    uint32_t ks2 = k0 ^ k1 ^ 0x1BD11BDAu;
#define TF_R(r) { x0 += x1; x1 = (x1 << (r)) | (x1 >> (32 - (r))); x1 ^= x0; }
    x0 += k0; x1 += k1;
    TF_R(13) TF_R(15) TF_R(26) TF_R(6)   x0 += k1;  x1 += ks2 + 1u;
    TF_R(17) TF_R(29) TF_R(16) TF_R(24)  x0 += ks2; x1 += k0  + 2u;
    TF_R(13) TF_R(15) TF_R(26) TF_R(6)   x0 += k0;  x1 += k1  + 3u;
    TF_R(17) TF_R(29) TF_R(16) TF_R(24)  x0 += k1;  x1 += ks2 + 4u;
    TF_R(13) TF_R(15) TF_R(26) TF_R(6)   x0 += ks2; x1 += k0  + 5u;
#undef TF_R
}

__device__ __forceinline__ bool drop_keep(uint32_t k0, uint32_t k1, uint32_t idx) {
    uint32_t x0 = 0u, x1 = idx;
    tf2x32(k0, k1, x0, x1);
    return ((x0 ^ x1) & 0x80000000u) == 0u;
}

// warp-collective 64-bit keep mask for `node`
__device__ __forceinline__ ull gen_mask_word(uint32_t k0, uint32_t k1, int node) {
    int lane = threadIdx.x & 31;
    uint32_t base = (uint32_t)node * (uint32_t)HID;
    bool b0 = drop_keep(k0, k1, base + (uint32_t)lane);
    bool b1 = drop_keep(k0, k1, base + 32u + (uint32_t)lane);
    uint32_t lo = __ballot_sync(0xffffffffu, b0);
    uint32_t hi = __ballot_sync(0xffffffffu, b1);
    return ((ull)hi << 32) | (ull)lo;
}

// ---------------- launch 0: degree + scan + CSR fill (persistent, 98 blocks) ----
__global__ __launch_bounds__(SCAN_B) void k_degscan(const int* __restrict__ src,
                                                    const int* __restrict__ dst) {
    __shared__ int wsum[32];
    __shared__ int sOff;
    int t = threadIdx.x, b = blockIdx.x;
    int lane = t & 31, wid = t >> 5;

    // ---- phase 1: degree count ----
    for (int e = b * SCAN_B + t; e < N_EDGES; e += NSCANB * SCAN_B)
        atomicAdd(&g_deg[dst[e]], 1);
    __syncthreads();
    if (t == 0) {
        __threadfence();
        atomicAdd(&g_arrive1, 1);
        while (atomicAdd(&g_arrive1, 0) < NSCANB) {}
    }
    __syncthreads();

    // ---- phase 2: scan ----
    int i = b * SCAN_B + t;
    int v = (i < N_NODES) ? *(volatile int*)&g_deg[i] : 0;
    int x = v;
#pragma unroll
    for (int o = 1; o < 32; o <<= 1) {
        int y = __shfl_up_sync(0xffffffffu, x, o);
        if (lane >= o) x += y;
    }
    if (lane == 31) wsum[wid] = x;
    __syncthreads();
    if (wid == 0) {
        int s = wsum[lane];
#pragma unroll
        for (int o = 1; o < 32; o <<= 1) {
            int y = __shfl_up_sync(0xffffffffu, s, o);
            if (lane >= o) s += y;
        }
        wsum[lane] = s;
    }
    __syncthreads();
    int incl = x + (wid ? wsum[wid - 1] : 0);
    if (t == SCAN_B - 1) {
        *(volatile int*)&g_bsum[b] = incl;
        __threadfence();
        atomicAdd(&g_arrive2, 1);
    }
    if (b == 0) {
        if (t == 0) {
            while (atomicAdd(&g_arrive2, 0) < NSCANB) {}
        }
        __syncthreads();
        if (wid == 0) {
            __threadfence();
            int vals[4];
            int tot = 0;
#pragma unroll
            for (int j = 0; j < 4; j++) {
                int idx = lane * 4 + j;
                int bv = (idx < NSCANB) ? *(volatile int*)&g_bsum[idx] : 0;
                tot += bv;
                vals[j] = tot;
            }
            int ex = tot;
#pragma unroll
            for (int o = 1; o < 32; o <<= 1) {
                int y = __shfl_up_sync(0xffffffffu, ex, o);
                if (lane >= o) ex += y;
            }
            ex -= tot;
#pragma unroll
            for (int j = 0; j < 4; j++) {
                int idx = lane * 4 + j;
                if (idx < NSCANB)
                    *(volatile int*)&g_boff[idx] = ex + (j ? vals[j - 1] : 0);
            }
            __threadfence();
        }
        __syncthreads();
        if (t == 0) atomicExch(&g_flag, 1);
    }
    if (t == 0) {
        while (atomicAdd(&g_flag, 0) == 0) {}
        __threadfence();
        sOff = *(volatile int*)&g_boff[b];
    }
    __syncthreads();
    int boff = sOff;
    if (i < N_NODES) {
        *(volatile int*)&g_rowptr[i + 1] = incl + boff;
        g_norm[i] = rsqrtf((float)(v + 1));
    }
    if (b == 0 && t == 0) *(volatile int*)&g_rowptr[0] = 0;

    // ---- phase 3 handshake: rowptr complete everywhere ----
    __syncthreads();
    if (t == 0) {
        __threadfence();
        atomicAdd(&g_arrive3, 1);
        while (atomicAdd(&g_arrive3, 0) < NSCANB) {}
        __threadfence();
    }
    __syncthreads();

    // ---- phase 3: CSR fill ----
    for (int e = b * SCAN_B + t; e < N_EDGES; e += NSCANB * SCAN_B) {
        int d = dst[e];
        int ofs = atomicAdd(&g_cnt[d], 1);
        g_csr[*(volatile int*)&g_rowptr[d] + ofs] = src[e] * ROW_BYTES;
    }
}

// ---------------- launch 1: gemm1 (FFMA2, K-chunks of 32, 8 syncs) --------------
__global__ __launch_bounds__(256) void k_gemm1(const float* __restrict__ feat,
                                               const float* __restrict__ w1) {
    __shared__ float sA[32][132];
    __shared__ float sB[32][64];
    int tid = threadIdx.x;
    int nb  = blockIdx.x * 128;
    int tx  = tid & 15;
    int ty  = tid >> 4;
    ull acc2[4][4];
#pragma unroll
    for (int p = 0; p < 4; p++)
#pragma unroll
        for (int c = 0; c < 4; c++) acc2[p][c] = 0ull;

#pragma unroll
    for (int kc = 0; kc < 4; kc++) {
#pragma unroll
        for (int l = 0; l < 4; l++) {
            int idx = tid + l * 256;         // 0..1023
            int nd  = idx >> 3;              // node 0..127
            int kq  = idx & 7;               // float4 group within 32 k
            int gn  = nb + nd;
            float4 v = make_float4(0.f, 0.f, 0.f, 0.f);
            if (gn < N_NODES)
                v = *reinterpret_cast<const float4*>(&feat[(size_t)gn * IN_DIM + kc * 32 + kq * 4]);
            sA[kq * 4 + 0][nd] = v.x;
            sA[kq * 4 + 1][nd] = v.y;
            sA[kq * 4 + 2][nd] = v.z;
            sA[kq * 4 + 3][nd] = v.w;
        }
#pragma unroll
        for (int l = 0; l < 2; l++) {
            int idx = tid + l * 256;         // 0..511
            int kk = idx >> 4, c4 = idx & 15;
            float4 v = *reinterpret_cast<const float4*>(&w1[(kc * 32 + kk) * HID + c4 * 4]);
            *reinterpret_cast<float4*>(&sB[kk][c4 * 4]) = v;
        }
        __syncthreads();
#pragma unroll
        for (int kk = 0; kk < 32; kk++) {
            float4 b = *reinterpret_cast<float4*>(&sB[kk][tx * 4]);
            ull bb[4];
            bb[0] = pack2(b.x, b.x); bb[1] = pack2(b.y, b.y);
            bb[2] = pack2(b.z, b.z); bb[3] = pack2(b.w, b.w);
            longlong2 aA = *reinterpret_cast<longlong2*>(&sA[kk][ty * 8]);
            longlong2 aB = *reinterpret_cast<longlong2*>(&sA[kk][ty * 8 + 4]);
            ull ap[4] = {(ull)aA.x, (ull)aA.y, (ull)aB.x, (ull)aB.y};
#pragma unroll
            for (int p = 0; p < 4; p++) {
                fma2(acc2[p][0], ap[p], bb[0]);
                fma2(acc2[p][1], ap[p], bb[1]);
                fma2(acc2[p][2], ap[p], bb[2]);
                fma2(acc2[p][3], ap[p], bb[3]);
            }
        }
        __syncthreads();
    }
#pragma unroll
    for (int p = 0; p < 4; p++) {
        float lo[4], hi[4];
#pragma unroll
        for (int c = 0; c < 4; c++) unpack2(acc2[p][c], lo[c], hi[c]);
        int gn0 = nb + ty * 8 + 2 * p;
        int gn1 = gn0 + 1;
        if (gn0 < N_NODES) {
            float nm = g_norm[gn0];
            float4 v = make_float4(lo[0] * nm, lo[1] * nm, lo[2] * nm, lo[3] * nm);
            *reinterpret_cast<float4*>(&g_t[(size_t)gn0 * HID + tx * 4]) = v;
        }
        if (gn1 < N_NODES) {
            float nm = g_norm[gn1];
            float4 v = make_float4(hi[0] * nm, hi[1] * nm, hi[2] * nm, hi[3] * nm);
            *reinterpret_cast<float4*>(&g_t[(size_t)gn1 * HID + tx * 4]) = v;
        }
    }
}

// ---------------- launches 2,3: gather --------------------------------------------
// FIN=1: fused fin1 epilogue with inline threefry (latency slack absorbs it).
// FIN=0: raw sum + generates g_mask2[w] + zeroes colsum.   (launch 3 = ncu slot)
template<int FIN>
__global__ __launch_bounds__(256) void k_gather(const float* __restrict__ sbuf,
                                                float* __restrict__ obuf,
                                                uint32_t k0, uint32_t k1) {
    if (FIN == 0 && blockIdx.x == 0 && threadIdx.x < HID)
        g_colsum[threadIdx.x] = 0.f;
    int w = (blockIdx.x * blockDim.x + threadIdx.x) >> 5;
    if (w >= N_NODES) return;
    int lane = threadIdx.x & 31;
    if (FIN == 0) {                          // dropout-2 mask for fin2
        ull m = gen_mask_word(k0, k1, w);
        if (lane == 0) g_mask2[w] = m;
    }
    int beg = g_rowptr[w], end = g_rowptr[w + 1];
    const char* sb = reinterpret_cast<const char*>(sbuf) + lane * 8;
    ull acc0 = *reinterpret_cast<const ull*>(sb + (size_t)w * ROW_BYTES);  // self loop
    ull acc1 = 0ull;
    for (int base = beg; base < end; base += 32) {
        int j = base + lane;
        int off = (j < end) ? g_csr[j] : 0;
        int cnt = min(32, end - base);
#pragma unroll 8
        for (int t = 0; t < cnt; t++) {
            int so = __shfl_sync(0xffffffffu, off, t);
            ull v = *reinterpret_cast<const ull*>(sb + (unsigned)so);
            if (t & 1) add2(acc1, v); else add2(acc0, v);
        }
    }
    add2(acc0, acc1);
    float ax, ay;
    unpack2(acc0, ax, ay);
    if (FIN == 1) {
        float nw = g_norm[w];
        ax = fmaxf(ax * nw, 0.f);
        ay = fmaxf(ay * nw, 0.f);
        uint32_t idx = (uint32_t)w * HID + (uint32_t)(lane * 2);
        ax = drop_keep(k0, k1, idx)     ? 2.f * ax : 0.f;
        ay = drop_keep(k0, k1, idx + 1) ? 2.f * ay : 0.f;
        ax *= nw; ay *= nw;
    }
    *reinterpret_cast<float2*>(&obuf[(size_t)w * HID + lane * 2]) = make_float2(ax, ay);
}

// ---------------- launch 4: fin2 (64 nodes/block, FFMA2, mask from g_mask2) -----
__global__ __launch_bounds__(512) void k_fin2(const float* __restrict__ w2) {
    __shared__ float sW[64 * 64];
    __shared__ float sIn[64 * 64];
    __shared__ float sPart[8][65];
    int tid = threadIdx.x;
    int nb = blockIdx.x * 64;
#pragma unroll
    for (int l = 0; l < 2; l++) {
        int i = (tid + l * 512) * 4;
        *reinterpret_cast<float4*>(&sW[i]) = *reinterpret_cast<const float4*>(&w2[i]);
    }
#pragma unroll
    for (int l = 0; l < 2; l++) {
        int i = (tid + l * 512) * 4;
        int n = i >> 6;
        float4 v = make_float4(0.f, 0.f, 0.f, 0.f);
        if (nb + n < N_NODES)
            v = *reinterpret_cast<const float4*>(&g_agg2[(size_t)(nb + n) * HID + (i & 63)]);
        *reinterpret_cast<float4*>(&sIn[i]) = v;
    }
    __syncthreads();
    int n  = tid >> 3;
    int cg = tid & 7;
    ull acc2[4] = {0ull, 0ull, 0ull, 0ull};
    const float* a = &sIn[n * 64];
#pragma unroll
    for (int k = 0; k < 64; k++) {
        ull av2 = pack2(a[k], a[k]);
        const ull* bp = reinterpret_cast<const ull*>(&sW[k * 64 + cg * 8]);
        fma2(acc2[0], av2, bp[0]);
        fma2(acc2[1], av2, bp[1]);
        fma2(acc2[2], av2, bp[2]);
        fma2(acc2[3], av2, bp[3]);
    }
    float accf[8];
#pragma unroll
    for (int j = 0; j < 4; j++) unpack2(acc2[j], accf[2 * j], accf[2 * j + 1]);
    int gn = nb + n;
    bool ok = (gn < N_NODES);
    float nm = ok ? g_norm[gn] : 0.f;
    ull m = ok ? (g_mask2[gn] >> (cg * 8)) : 0ull;
    float vout[8];
#pragma unroll
    for (int c = 0; c < 8; c++) {
        float v = fmaxf(accf[c] * nm, 0.f);
        v = ((m >> c) & 1ull) ? 2.f * v : 0.f;
        vout[c] = v;
    }
    if (ok) {
        *reinterpret_cast<float4*>(&g_h2[(size_t)gn * HID + cg * 8]) =
            make_float4(vout[0], vout[1], vout[2], vout[3]);
        *reinterpret_cast<float4*>(&g_h2[(size_t)gn * HID + cg * 8 + 4]) =
            make_float4(vout[4], vout[5], vout[6], vout[7]);
    }
    __syncthreads();
    float* sOut = sW;
#pragma unroll
    for (int c = 0; c < 8; c++)
        sOut[n * 64 + cg * 8 + c] = ok ? vout[c] : 0.f;
    __syncthreads();
    {
        int c = tid & 63, chunk = tid >> 6;
        float s = 0.f;
#pragma unroll
        for (int i = 0; i < 8; i++) s += sOut[(chunk * 8 + i) * 64 + c];
        sPart[chunk][c] = s;
    }
    __syncthreads();
    if (tid < 64) {
        float s = 0.f;
#pragma unroll
        for (int i = 0; i < 8; i++) s += sPart[i][tid];
        atomicAdd(&g_colsum[tid], s);
    }
}

// ---------------- launch 5: conv + radius + clip + next-run cleanup --------------
__global__ void k_final(const float* __restrict__ cw, const float* __restrict__ cb,
                        const float* __restrict__ ref, float* __restrict__ out) {
    __shared__ float sO[CONVOUT];
    __shared__ float m[64];
    int tid = threadIdx.x;
    if (tid < 64) m[tid] = g_colsum[tid] * (1.f / (float)N_NODES);
    __syncthreads();
    if (tid < CONVOUT) {
        int o = tid / 62, jj = tid % 62;
        sO[tid] = cw[o * 3 + 0] * m[jj] + cw[o * 3 + 1] * m[jj + 1]
                + cw[o * 3 + 2] * m[jj + 2] + cb[o];
    }
    __syncthreads();
    int lane = tid & 31, warp = tid >> 5;
    int node = blockIdx.x * 8 + warp;
    float w00 = cw[0], w01 = cw[1], w02 = cw[2];
    float w10 = cw[3], w11 = cw[4], w12 = cw[5];
    float b0 = cb[0], b1 = cb[1];
    const float* h = &g_h2[(size_t)node * HID];
    float acc = 0.f;
#pragma unroll
    for (int l = 0; l < 4; l++) {
        int j = lane * 4 + l;
        if (j < CONVOUT) {
            float y;
            if (j < 62) y = w00 * h[j] + w01 * h[j + 1] + w02 * h[j + 2] + b0;
            else { int jj = j - 62; y = w10 * h[jj] + w11 * h[jj + 1] + w12 * h[jj + 2] + b1; }
            float d = y - sO[j] + 1e-6f;
            acc += d * d;
        }
    }
#pragma unroll
    for (int o = 16; o; o >>= 1) acc += __shfl_xor_sync(0xffffffffu, acc, o);
    if (lane == 0) {
        float r = sqrtf(acc);
        out[node] = fminf(fmaxf(r - ref[0], 1e-4f), 0.9999f);
    }
    if (blockIdx.x == 0 && tid == 0) out[N_NODES] = ref[0];
    int gid = blockIdx.x * blockDim.x + tid;
    if (gid < N_NODES) { g_deg[gid] = 0; g_cnt[gid] = 0; }
    if (gid == 0) { g_arrive1 = 0; g_arrive2 = 0; g_arrive3 = 0; g_flag = 0; }
}

// ---------------- launch -----------------------------------------------------------
extern "C" void kernel_launch(void* const* d_in, const int* in_sizes, int n_in,
                              void* d_out, int out_size) {
    const float* feat = (const float*)d_in[0];
    const float* w1   = (const float*)d_in[1];
    const float* w2   = (const float*)d_in[2];
    const float* cw   = (const float*)d_in[3];
    const float* cb   = (const float*)d_in[4];
    const float* ref  = (const float*)d_in[5];
    const int*   src  = (const int*)d_in[6];
    const int*   dst  = (const int*)d_in[7];
    float* out = (float*)d_out;

    uint32_t ka0 = 0, ka1 = 0, kb0 = 0, kb1 = 1;
    tf2x32(0u, 42u, ka0, ka1);
    tf2x32(0u, 42u, kb0, kb1);

    float* t_ptr;   cudaGetSymbolAddress((void**)&t_ptr, g_t);
    float* h1_ptr;  cudaGetSymbolAddress((void**)&h1_ptr, g_h1);
    float* a2_ptr;  cudaGetSymbolAddress((void**)&a2_ptr, g_agg2);

    k_degscan<<<NSCANB, SCAN_B>>>(src, dst);                                   // 0
    k_gemm1<<<(N_NODES + 127) / 128, 256>>>(feat, w1);                         // 1
    k_gather<1><<<(N_NODES * 32 + 255) / 256, 256>>>(t_ptr, h1_ptr, ka0, ka1); // 2
    k_gather<0><<<(N_NODES * 32 + 255) / 256, 256>>>(h1_ptr, a2_ptr, kb0, kb1);// 3 <- ncu slot
    k_fin2<<<(N_NODES + 63) / 64, 512>>>(w2);                                  // 4
    k_final<<<N_NODES / 8, 256>>>(cw, cb, ref, out);                           // 5
}

// round 14
// speedup vs baseline: 1.0275x; 1.0275x over previous
#include <cuda_runtime.h>
#include <cstdint>

#define N_NODES 100000
#define N_EDGES 1600000
#define IN_DIM  128
#define HID     64
#define ROW_BYTES (HID * 4)   // 256
#define CONVOUT 124   // 2 * 62
#define SCAN_B  1024
#define NSCANB  ((N_NODES + SCAN_B - 1) / SCAN_B)   // 98

typedef unsigned long long ull;

// ---------------- packed f32x2 helpers (Blackwell FFMA2/FADD2) -----------------
__device__ __forceinline__ ull pack2(float x, float y) {
    ull r;
    asm("mov.b64 %0, {%1, %2};" : "=l"(r) : "f"(x), "f"(y));
    return r;
}
__device__ __forceinline__ void unpack2(ull v, float& x, float& y) {
    asm("mov.b64 {%0, %1}, %2;" : "=f"(x), "=f"(y) : "l"(v));
}
__device__ __forceinline__ void fma2(ull& d, ull a, ull b) {
    asm("fma.rn.f32x2 %0, %1, %2, %0;" : "+l"(d) : "l"(a), "l"(b));
}
__device__ __forceinline__ void add2(ull& d, ull a) {
    asm("add.rn.f32x2 %0, %0, %1;" : "+l"(d) : "l"(a));
}

// ---------------- scratch (static device globals; zero at module load) ---------
__device__ float g_t   [N_NODES * HID];   // (feat@w1)*norm
__device__ float g_h1  [N_NODES * HID];   // dropout(relu(agg*norm))*norm
__device__ float g_agg2[N_NODES * HID];   // layer-2 aggregate
__device__ float g_h2  [N_NODES * HID];   // final node features
__device__ int   g_deg [N_NODES];         // zeroed by k_final tail
__device__ int   g_cnt [N_NODES];         // set = rowptr[i] by degscan emit phase
__device__ float g_norm[N_NODES];
__device__ int   g_rowptr[N_NODES + 1];
__device__ int   g_bsum[NSCANB];
__device__ int   g_boff[NSCANB];
__device__ int   g_csr[N_EDGES];          // BYTE offsets of src rows, grouped by dst
__device__ ull   g_mask2[N_NODES];        // dropout-2 keep bits (written by gather<0>)
__device__ float g_colsum[HID];           // zeroed in k_gather<0>
__device__ int   g_arrive1;               // deg-phase handshake
__device__ int   g_arrive2;               // bsum handshake
__device__ int   g_flag;                  // boff release

// ---------------- threefry2x32 (20 rounds, JAX-compatible) --------------------
__host__ __device__ __forceinline__ void tf2x32(uint32_t k0, uint32_t k1,
                                                uint32_t& x0, uint32_t& x1) {
    uint32_t ks2 = k0 ^ k1 ^ 0x1BD11BDAu;
#define TF_R(r) { x0 += x1; x1 = (x1 << (r)) | (x1 >> (32 - (r))); x1 ^= x0; }
    x0 += k0; x1 += k1;
    TF_R(13) TF_R(15) TF_R(26) TF_R(6)   x0 += k1;  x1 += ks2 + 1u;
    TF_R(17) TF_R(29) TF_R(16) TF_R(24)  x0 += ks2; x1 += k0  + 2u;
    TF_R(13) TF_R(15) TF_R(26) TF_R(6)   x0 += k0;  x1 += k1  + 3u;
    TF_R(17) TF_R(29) TF_R(16) TF_R(24)  x0 += k1;  x1 += ks2 + 4u;
    TF_R(13) TF_R(15) TF_R(26) TF_R(6)   x0 += ks2; x1 += k0  + 5u;
#undef TF_R
}

__device__ __forceinline__ bool drop_keep(uint32_t k0, uint32_t k1, uint32_t idx) {
    uint32_t x0 = 0u, x1 = idx;
    tf2x32(k0, k1, x0, x1);
    return ((x0 ^ x1) & 0x80000000u) == 0u;
}

// warp-collective 64-bit keep mask for `node`
__device__ __forceinline__ ull gen_mask_word(uint32_t k0, uint32_t k1, int node) {
    int lane = threadIdx.x & 31;
    uint32_t base = (uint32_t)node * (uint32_t)HID;
    bool b0 = drop_keep(k0, k1, base + (uint32_t)lane);
    bool b1 = drop_keep(k0, k1, base + 32u + (uint32_t)lane);
    uint32_t lo = __ballot_sync(0xffffffffu, b0);
    uint32_t hi = __ballot_sync(0xffffffffu, b1);
    return ((ull)hi << 32) | (ull)lo;
}

// ---------------- launch 0: degree + scan (persistent, 98 blocks) ---------------
__global__ __launch_bounds__(SCAN_B) void k_degscan(const int* __restrict__ dst) {
    __shared__ int wsum[32];
    __shared__ int sOff;
    int t = threadIdx.x, b = blockIdx.x;
    int lane = t & 31, wid = t >> 5;

    // ---- phase 1: degree count ----
    for (int e = b * SCAN_B + t; e < N_EDGES; e += NSCANB * SCAN_B)
        atomicAdd(&g_deg[dst[e]], 1);
    __syncthreads();
    if (t == 0) {
        __threadfence();
        atomicAdd(&g_arrive1, 1);
        while (atomicAdd(&g_arrive1, 0) < NSCANB) {}
    }
    __syncthreads();

    // ---- phase 2: scan ----
    int i = b * SCAN_B + t;
    int v = (i < N_NODES) ? *(volatile int*)&g_deg[i] : 0;
    int x = v;
#pragma unroll
    for (int o = 1; o < 32; o <<= 1) {
        int y = __shfl_up_sync(0xffffffffu, x, o);
        if (lane >= o) x += y;
    }
    if (lane == 31) wsum[wid] = x;
    __syncthreads();
    if (wid == 0) {
        int s = wsum[lane];
#pragma unroll
        for (int o = 1; o < 32; o <<= 1) {
            int y = __shfl_up_sync(0xffffffffu, s, o);
            if (lane >= o) s += y;
        }
        wsum[lane] = s;
    }
    __syncthreads();
    int incl = x + (wid ? wsum[wid - 1] : 0);
    if (t == SCAN_B - 1) {
        *(volatile int*)&g_bsum[b] = incl;
        __threadfence();
        atomicAdd(&g_arrive2, 1);
    }
    // block 0 warp 0 scans block totals (shuffle-only)
    if (b == 0) {
        if (t == 0) {
            while (atomicAdd(&g_arrive2, 0) < NSCANB) {}
        }
        __syncthreads();
        if (wid == 0) {
            __threadfence();
            int vals[4];
            int tot = 0;
#pragma unroll
            for (int j = 0; j < 4; j++) {
                int idx = lane * 4 + j;
                int bv = (idx < NSCANB) ? *(volatile int*)&g_bsum[idx] : 0;
                tot += bv;
                vals[j] = tot;
            }
            int ex = tot;
#pragma unroll
            for (int o = 1; o < 32; o <<= 1) {
                int y = __shfl_up_sync(0xffffffffu, ex, o);
                if (lane >= o) ex += y;
            }
            ex -= tot;
#pragma unroll
            for (int j = 0; j < 4; j++) {
                int idx = lane * 4 + j;
                if (idx < NSCANB)
                    *(volatile int*)&g_boff[idx] = ex + (j ? vals[j - 1] : 0);
            }
            __threadfence();
        }
        __syncthreads();
        if (t == 0) atomicExch(&g_flag, 1);
    }
    if (t == 0) {
        while (atomicAdd(&g_flag, 0) == 0) {}
        __threadfence();
        sOff = *(volatile int*)&g_boff[b];
    }
    __syncthreads();
    int boff = sOff;
    if (i < N_NODES) {
        int excl = incl + boff - v;        // rowptr[i]
        g_rowptr[i + 1] = incl + boff;
        g_cnt[i] = excl;                   // fill slots start here (no rowptr load in fill)
        g_norm[i] = rsqrtf((float)(v + 1));
    }
    if (b == 0 && t == 0) g_rowptr[0] = 0;
}

// ---------------- launch 1: CSR fill (full chip, slot via g_cnt directly) -------
__global__ void k_fill(const int* __restrict__ src, const int* __restrict__ dst) {
    int e = blockIdx.x * blockDim.x + threadIdx.x;
    if (e >= N_EDGES) return;
    int slot = atomicAdd(&g_cnt[dst[e]], 1);
    g_csr[slot] = src[e] * ROW_BYTES;
}

// ---------------- launch 2: gemm1 (FFMA2, K-chunks of 32, 4 sync pairs) ---------
__global__ __launch_bounds__(256) void k_gemm1(const float* __restrict__ feat,
                                               const float* __restrict__ w1) {
    __shared__ float sA[32][132];
    __shared__ float sB[32][64];
    int tid = threadIdx.x;
    int nb  = blockIdx.x * 128;
    int tx  = tid & 15;
    int ty  = tid >> 4;
    ull acc2[4][4];
#pragma unroll
    for (int p = 0; p < 4; p++)
#pragma unroll
        for (int c = 0; c < 4; c++) acc2[p][c] = 0ull;

#pragma unroll
    for (int kc = 0; kc < 4; kc++) {
#pragma unroll
        for (int l = 0; l < 4; l++) {
            int idx = tid + l * 256;
            int nd  = idx >> 3;
            int kq  = idx & 7;
            int gn  = nb + nd;
            float4 v = make_float4(0.f, 0.f, 0.f, 0.f);
            if (gn < N_NODES)
                v = *reinterpret_cast<const float4*>(&feat[(size_t)gn * IN_DIM + kc * 32 + kq * 4]);
            sA[kq * 4 + 0][nd] = v.x;
            sA[kq * 4 + 1][nd] = v.y;
            sA[kq * 4 + 2][nd] = v.z;
            sA[kq * 4 + 3][nd] = v.w;
        }
#pragma unroll
        for (int l = 0; l < 2; l++) {
            int idx = tid + l * 256;
            int kk = idx >> 4, c4 = idx & 15;
            float4 v = *reinterpret_cast<const float4*>(&w1[(kc * 32 + kk) * HID + c4 * 4]);
            *reinterpret_cast<float4*>(&sB[kk][c4 * 4]) = v;
        }
        __syncthreads();
#pragma unroll
        for (int kk = 0; kk < 32; kk++) {
            float4 b = *reinterpret_cast<float4*>(&sB[kk][tx * 4]);
            ull bb[4];
            bb[0] = pack2(b.x, b.x); bb[1] = pack2(b.y, b.y);
            bb[2] = pack2(b.z, b.z); bb[3] = pack2(b.w, b.w);
            longlong2 aA = *reinterpret_cast<longlong2*>(&sA[kk][ty * 8]);
            longlong2 aB = *reinterpret_cast<longlong2*>(&sA[kk][ty * 8 + 4]);
            ull ap[4] = {(ull)aA.x, (ull)aA.y, (ull)aB.x, (ull)aB.y};
#pragma unroll
            for (int p = 0; p < 4; p++) {
                fma2(acc2[p][0], ap[p], bb[0]);
                fma2(acc2[p][1], ap[p], bb[1]);
                fma2(acc2[p][2], ap[p], bb[2]);
                fma2(acc2[p][3], ap[p], bb[3]);
            }
        }
        __syncthreads();
    }
#pragma unroll
    for (int p = 0; p < 4; p++) {
        float lo[4], hi[4];
#pragma unroll
        for (int c = 0; c < 4; c++) unpack2(acc2[p][c], lo[c], hi[c]);
        int gn0 = nb + ty * 8 + 2 * p;
        int gn1 = gn0 + 1;
        if (gn0 < N_NODES) {
            float nm = g_norm[gn0];
            float4 v = make_float4(lo[0] * nm, lo[1] * nm, lo[2] * nm, lo[3] * nm);
            *reinterpret_cast<float4*>(&g_t[(size_t)gn0 * HID + tx * 4]) = v;
        }
        if (gn1 < N_NODES) {
            float nm = g_norm[gn1];
            float4 v = make_float4(hi[0] * nm, hi[1] * nm, hi[2] * nm, hi[3] * nm);
            *reinterpret_cast<float4*>(&g_t[(size_t)gn1 * HID + tx * 4]) = v;
        }
    }
}

// ---------------- launches 3,4: gather --------------------------------------------
// FIN=1 (launch 3 = ncu slot): fused fin1 epilogue with inline threefry.
// FIN=0: raw sum + generates g_mask2[w] + zeroes colsum.
template<int FIN>
__global__ __launch_bounds__(256) void k_gather(const float* __restrict__ sbuf,
                                                float* __restrict__ obuf,
                                                uint32_t k0, uint32_t k1) {
    if (FIN == 0 && blockIdx.x == 0 && threadIdx.x < HID)
        g_colsum[threadIdx.x] = 0.f;
    int w = (blockIdx.x * blockDim.x + threadIdx.x) >> 5;
    if (w >= N_NODES) return;
    int lane = threadIdx.x & 31;
    if (FIN == 0) {
        ull m = gen_mask_word(k0, k1, w);
        if (lane == 0) g_mask2[w] = m;
    }
    int beg = g_rowptr[w], end = g_rowptr[w + 1];
    const char* sb = reinterpret_cast<const char*>(sbuf) + lane * 8;
    ull acc0 = *reinterpret_cast<const ull*>(sb + (size_t)w * ROW_BYTES);  // self loop
    ull acc1 = 0ull;
    for (int base = beg; base < end; base += 32) {
        int j = base + lane;
        int off = (j < end) ? g_csr[j] : 0;
        int cnt = min(32, end - base);
#pragma unroll 8
        for (int t = 0; t < cnt; t++) {
            int so = __shfl_sync(0xffffffffu, off, t);
            ull v = *reinterpret_cast<const ull*>(sb + (unsigned)so);
            if (t & 1) add2(acc1, v); else add2(acc0, v);
        }
    }
    add2(acc0, acc1);
    float ax, ay;
    unpack2(acc0, ax, ay);
    if (FIN == 1) {
        float nw = g_norm[w];
        ax = fmaxf(ax * nw, 0.f);
        ay = fmaxf(ay * nw, 0.f);
        uint32_t idx = (uint32_t)w * HID + (uint32_t)(lane * 2);
        ax = drop_keep(k0, k1, idx)     ? 2.f * ax : 0.f;
        ay = drop_keep(k0, k1, idx + 1) ? 2.f * ay : 0.f;
        ax *= nw; ay *= nw;
    }
    *reinterpret_cast<float2*>(&obuf[(size_t)w * HID + lane * 2]) = make_float2(ax, ay);
}

// ---------------- launch 5: fin2 (64 nodes/block, FFMA2, mask from g_mask2) -----
__global__ __launch_bounds__(512) void k_fin2(const float* __restrict__ w2) {
    __shared__ float sW[64 * 64];
    __shared__ float sIn[64 * 64];
    __shared__ float sPart[8][65];
    int tid = threadIdx.x;
    int nb = blockIdx.x * 64;
#pragma unroll
    for (int l = 0; l < 2; l++) {
        int i = (tid + l * 512) * 4;
        *reinterpret_cast<float4*>(&sW[i]) = *reinterpret_cast<const float4*>(&w2[i]);
    }
#pragma unroll
    for (int l = 0; l < 2; l++) {
        int i = (tid + l * 512) * 4;
        int n = i >> 6;
        float4 v = make_float4(0.f, 0.f, 0.f, 0.f);
        if (nb + n < N_NODES)
            v = *reinterpret_cast<const float4*>(&g_agg2[(size_t)(nb + n) * HID + (i & 63)]);
        *reinterpret_cast<float4*>(&sIn[i]) = v;
    }
    __syncthreads();
    int n  = tid >> 3;
    int cg = tid & 7;
    ull acc2[4] = {0ull, 0ull, 0ull, 0ull};
    const float* a = &sIn[n * 64];
#pragma unroll
    for (int k = 0; k < 64; k++) {
        ull av2 = pack2(a[k], a[k]);
        const ull* bp = reinterpret_cast<const ull*>(&sW[k * 64 + cg * 8]);
        fma2(acc2[0], av2, bp[0]);
        fma2(acc2[1], av2, bp[1]);
        fma2(acc2[2], av2, bp[2]);
        fma2(acc2[3], av2, bp[3]);
    }
    float accf[8];
#pragma unroll
    for (int j = 0; j < 4; j++) unpack2(acc2[j], accf[2 * j], accf[2 * j + 1]);
    int gn = nb + n;
    bool ok = (gn < N_NODES);
    float nm = ok ? g_norm[gn] : 0.f;
    ull m = ok ? (g_mask2[gn] >> (cg * 8)) : 0ull;
    float vout[8];
#pragma unroll
    for (int c = 0; c < 8; c++) {
        float v = fmaxf(accf[c] * nm, 0.f);
        v = ((m >> c) & 1ull) ? 2.f * v : 0.f;
        vout[c] = v;
    }
    if (ok) {
        *reinterpret_cast<float4*>(&g_h2[(size_t)gn * HID + cg * 8]) =
            make_float4(vout[0], vout[1], vout[2], vout[3]);
        *reinterpret_cast<float4*>(&g_h2[(size_t)gn * HID + cg * 8 + 4]) =
            make_float4(vout[4], vout[5], vout[6], vout[7]);
    }
    __syncthreads();
    float* sOut = sW;
#pragma unroll
    for (int c = 0; c < 8; c++)
        sOut[n * 64 + cg * 8 + c] = ok ? vout[c] : 0.f;
    __syncthreads();
    {
        int c = tid & 63, chunk = tid >> 6;
        float s = 0.f;
#pragma unroll
        for (int i = 0; i < 8; i++) s += sOut[(chunk * 8 + i) * 64 + c];
        sPart[chunk][c] = s;
    }
    __syncthreads();
    if (tid < 64) {
        float s = 0.f;
#pragma unroll
        for (int i = 0; i < 8; i++) s += sPart[i][tid];
        atomicAdd(&g_colsum[tid], s);
    }
}

// ---------------- launch 6: conv + radius + clip + next-run cleanup --------------
__global__ void k_final(const float* __restrict__ cw, const float* __restrict__ cb,
                        const float* __restrict__ ref, float* __restrict__ out) {
    __shared__ float sO[CONVOUT];
    __shared__ float m[64];
    int tid = threadIdx.x;
    if (tid < 64) m[tid] = g_colsum[tid] * (1.f / (float)N_NODES);
    __syncthreads();
    if (tid < CONVOUT) {
        int o = tid / 62, jj = tid % 62;
        sO[tid] = cw[o * 3 + 0] * m[jj] + cw[o * 3 + 1] * m[jj + 1]
                + cw[o * 3 + 2] * m[jj + 2] + cb[o];
    }
    __syncthreads();
    int lane = tid & 31, warp = tid >> 5;
    int node = blockIdx.x * 8 + warp;
    float w00 = cw[0], w01 = cw[1], w02 = cw[2];
    float w10 = cw[3], w11 = cw[4], w12 = cw[5];
    float b0 = cb[0], b1 = cb[1];
    const float* h = &g_h2[(size_t)node * HID];
    float acc = 0.f;
#pragma unroll
    for (int l = 0; l < 4; l++) {
        int j = lane * 4 + l;
        if (j < CONVOUT) {
            float y;
            if (j < 62) y = w00 * h[j] + w01 * h[j + 1] + w02 * h[j + 2] + b0;
            else { int jj = j - 62; y = w10 * h[jj] + w11 * h[jj + 1] + w12 * h[jj + 2] + b1; }
            float d = y - sO[j] + 1e-6f;
            acc += d * d;
        }
    }
#pragma unroll
    for (int o = 16; o; o >>= 1) acc += __shfl_xor_sync(0xffffffffu, acc, o);
    if (lane == 0) {
        float r = sqrtf(acc);
        out[node] = fminf(fmaxf(r - ref[0], 1e-4f), 0.9999f);
    }
    if (blockIdx.x == 0 && tid == 0) out[N_NODES] = ref[0];
    // cleanup for next execution (cnt is re-initialized by degscan; skip it)
    int gid = blockIdx.x * blockDim.x + tid;
    if (gid < N_NODES) g_deg[gid] = 0;
    if (gid == 0) { g_arrive1 = 0; g_arrive2 = 0; g_flag = 0; }
}

// ---------------- launch -----------------------------------------------------------
extern "C" void kernel_launch(void* const* d_in, const int* in_sizes, int n_in,
                              void* d_out, int out_size) {
    const float* feat = (const float*)d_in[0];
    const float* w1   = (const float*)d_in[1];
    const float* w2   = (const float*)d_in[2];
    const float* cw   = (const float*)d_in[3];
    const float* cb   = (const float*)d_in[4];
    const float* ref  = (const float*)d_in[5];
    const int*   src  = (const int*)d_in[6];
    const int*   dst  = (const int*)d_in[7];
    float* out = (float*)d_out;

    uint32_t ka0 = 0, ka1 = 0, kb0 = 0, kb1 = 1;
    tf2x32(0u, 42u, ka0, ka1);
    tf2x32(0u, 42u, kb0, kb1);

    float* t_ptr;   cudaGetSymbolAddress((void**)&t_ptr, g_t);
    float* h1_ptr;  cudaGetSymbolAddress((void**)&h1_ptr, g_h1);
    float* a2_ptr;  cudaGetSymbolAddress((void**)&a2_ptr, g_agg2);

    k_degscan<<<NSCANB, SCAN_B>>>(dst);                                        // 0
    k_fill<<<(N_EDGES + 255) / 256, 256>>>(src, dst);                          // 1
    k_gemm1<<<(N_NODES + 127) / 128, 256>>>(feat, w1);                         // 2
    k_gather<1><<<(N_NODES * 32 + 255) / 256, 256>>>(t_ptr, h1_ptr, ka0, ka1); // 3 <- ncu slot
    k_gather<0><<<(N_NODES * 32 + 255) / 256, 256>>>(h1_ptr, a2_ptr, kb0, kb1);// 4
    k_fin2<<<(N_NODES + 63) / 64, 512>>>(w2);                                  // 5
    k_final<<<N_NODES / 8, 256>>>(cw, cb, ref, out);                           // 6
}

// round 15
// speedup vs baseline: 1.0765x; 1.0476x over previous
#include <cuda_runtime.h>
#include <cstdint>

#define N_NODES 100000
#define N_EDGES 1600000
#define IN_DIM  128
#define HID     64
#define ROW_BYTES (HID * 4)   // 256
#define CONVOUT 124   // 2 * 62
#define SCAN_B  1024
#define NSCANB  ((N_NODES + SCAN_B - 1) / SCAN_B)   // 98

typedef unsigned long long ull;

// ---------------- packed f32x2 helpers (Blackwell FFMA2/FADD2) -----------------
__device__ __forceinline__ ull pack2(float x, float y) {
    ull r;
    asm("mov.b64 %0, {%1, %2};" : "=l"(r) : "f"(x), "f"(y));
    return r;
}
__device__ __forceinline__ void unpack2(ull v, float& x, float& y) {
    asm("mov.b64 {%0, %1}, %2;" : "=f"(x), "=f"(y) : "l"(v));
}
__device__ __forceinline__ void fma2(ull& d, ull a, ull b) {
    asm("fma.rn.f32x2 %0, %1, %2, %0;" : "+l"(d) : "l"(a), "l"(b));
}
__device__ __forceinline__ void add2(ull& d, ull a) {
    asm("add.rn.f32x2 %0, %0, %1;" : "+l"(d) : "l"(a));
}

// ---------------- scratch (static device globals; zero at module load) ---------
__device__ float g_t   [N_NODES * HID];   // feat@w1 raw, then *norm by k_scale
__device__ float g_h1  [N_NODES * HID];
__device__ float g_agg2[N_NODES * HID];
__device__ float g_h2  [N_NODES * HID];
__device__ int   g_deg [N_NODES];         // zeroed by k_final tail
__device__ int   g_cnt [N_NODES];         // set = rowptr[i] by degscan emit phase
__device__ float g_norm[N_NODES];
__device__ int   g_rowptr[N_NODES + 1];
__device__ int   g_bsum[NSCANB];
__device__ int   g_boff[NSCANB];
__device__ int   g_csr[N_EDGES];          // BYTE offsets of src rows, grouped by dst
__device__ ull   g_mask2[N_NODES];
__device__ float g_colsum[HID];           // zeroed in k_gather<0>
__device__ int   g_arrive1;
__device__ int   g_arrive2;
__device__ int   g_flag;

// ---------------- threefry2x32 (20 rounds, JAX-compatible) --------------------
__host__ __device__ __forceinline__ void tf2x32(uint32_t k0, uint32_t k1,
                                                uint32_t& x0, uint32_t& x1) {
    uint32_t ks2 = k0 ^ k1 ^ 0x1BD11BDAu;
#define TF_R(r) { x0 += x1; x1 = (x1 << (r)) | (x1 >> (32 - (r))); x1 ^= x0; }
    x0 += k0; x1 += k1;
    TF_R(13) TF_R(15) TF_R(26) TF_R(6)   x0 += k1;  x1 += ks2 + 1u;
    TF_R(17) TF_R(29) TF_R(16) TF_R(24)  x0 += ks2; x1 += k0  + 2u;
    TF_R(13) TF_R(15) TF_R(26) TF_R(6)   x0 += k0;  x1 += k1  + 3u;
    TF_R(17) TF_R(29) TF_R(16) TF_R(24)  x0 += k1;  x1 += ks2 + 4u;
    TF_R(13) TF_R(15) TF_R(26) TF_R(6)   x0 += ks2; x1 += k0  + 5u;
#undef TF_R
}

__device__ __forceinline__ bool drop_keep(uint32_t k0, uint32_t k1, uint32_t idx) {
    uint32_t x0 = 0u, x1 = idx;
    tf2x32(k0, k1, x0, x1);
    return ((x0 ^ x1) & 0x80000000u) == 0u;
}

__device__ __forceinline__ ull gen_mask_word(uint32_t k0, uint32_t k1, int node) {
    int lane = threadIdx.x & 31;
    uint32_t base = (uint32_t)node * (uint32_t)HID;
    bool b0 = drop_keep(k0, k1, base + (uint32_t)lane);
    bool b1 = drop_keep(k0, k1, base + 32u + (uint32_t)lane);
    uint32_t lo = __ballot_sync(0xffffffffu, b0);
    uint32_t hi = __ballot_sync(0xffffffffu, b1);
    return ((ull)hi << 32) | (ull)lo;
}

// ---------------- degree + scan (persistent, 98 blocks) -------------------------
__global__ __launch_bounds__(SCAN_B) void k_degscan(const int* __restrict__ dst) {
    __shared__ int wsum[32];
    __shared__ int sOff;
    int t = threadIdx.x, b = blockIdx.x;
    int lane = t & 31, wid = t >> 5;

    for (int e = b * SCAN_B + t; e < N_EDGES; e += NSCANB * SCAN_B)
        atomicAdd(&g_deg[dst[e]], 1);
    __syncthreads();
    if (t == 0) {
        __threadfence();
        atomicAdd(&g_arrive1, 1);
        while (atomicAdd(&g_arrive1, 0) < NSCANB) {}
    }
    __syncthreads();

    int i = b * SCAN_B + t;
    int v = (i < N_NODES) ? *(volatile int*)&g_deg[i] : 0;
    int x = v;
#pragma unroll
    for (int o = 1; o < 32; o <<= 1) {
        int y = __shfl_up_sync(0xffffffffu, x, o);
        if (lane >= o) x += y;
    }
    if (lane == 31) wsum[wid] = x;
    __syncthreads();
    if (wid == 0) {
        int s = wsum[lane];
#pragma unroll
        for (int o = 1; o < 32; o <<= 1) {
            int y = __shfl_up_sync(0xffffffffu, s, o);
            if (lane >= o) s += y;
        }
        wsum[lane] = s;
    }
    __syncthreads();
    int incl = x + (wid ? wsum[wid - 1] : 0);
    if (t == SCAN_B - 1) {
        *(volatile int*)&g_bsum[b] = incl;
        __threadfence();
        atomicAdd(&g_arrive2, 1);
    }
    if (b == 0) {
        if (t == 0) {
            while (atomicAdd(&g_arrive2, 0) < NSCANB) {}
        }
        __syncthreads();
        if (wid == 0) {
            __threadfence();
            int vals[4];
            int tot = 0;
#pragma unroll
            for (int j = 0; j < 4; j++) {
                int idx = lane * 4 + j;
                int bv = (idx < NSCANB) ? *(volatile int*)&g_bsum[idx] : 0;
                tot += bv;
                vals[j] = tot;
            }
            int ex = tot;
#pragma unroll
            for (int o = 1; o < 32; o <<= 1) {
                int y = __shfl_up_sync(0xffffffffu, ex, o);
                if (lane >= o) ex += y;
            }
            ex -= tot;
#pragma unroll
            for (int j = 0; j < 4; j++) {
                int idx = lane * 4 + j;
                if (idx < NSCANB)
                    *(volatile int*)&g_boff[idx] = ex + (j ? vals[j - 1] : 0);
            }
            __threadfence();
        }
        __syncthreads();
        if (t == 0) atomicExch(&g_flag, 1);
    }
    if (t == 0) {
        while (atomicAdd(&g_flag, 0) == 0) {}
        __threadfence();
        sOff = *(volatile int*)&g_boff[b];
    }
    __syncthreads();
    int boff = sOff;
    if (i < N_NODES) {
        int inclg = incl + boff;
        g_rowptr[i + 1] = inclg;
        g_cnt[i] = inclg - v;              // rowptr[i]: fill slots start here
        g_norm[i] = rsqrtf((float)(v + 1));
    }
    if (b == 0 && t == 0) g_rowptr[0] = 0;
}

// ---------------- CSR fill (full chip, slot via g_cnt) --------------------------
__global__ void k_fill(const int* __restrict__ src, const int* __restrict__ dst) {
    int e = blockIdx.x * blockDim.x + threadIdx.x;
    if (e >= N_EDGES) return;
    int slot = atomicAdd(&g_cnt[dst[e]], 1);
    g_csr[slot] = src[e] * ROW_BYTES;
}

// ---------------- gemm1 RAW (no norm -> runs concurrently with degscan) ---------
__global__ __launch_bounds__(256) void k_gemm1(const float* __restrict__ feat,
                                               const float* __restrict__ w1) {
    __shared__ float sA[32][132];
    __shared__ float sB[32][64];
    int tid = threadIdx.x;
    int nb  = blockIdx.x * 128;
    int tx  = tid & 15;
    int ty  = tid >> 4;
    ull acc2[4][4];
#pragma unroll
    for (int p = 0; p < 4; p++)
#pragma unroll
        for (int c = 0; c < 4; c++) acc2[p][c] = 0ull;

#pragma unroll
    for (int kc = 0; kc < 4; kc++) {
#pragma unroll
        for (int l = 0; l < 4; l++) {
            int idx = tid + l * 256;
            int nd  = idx >> 3;
            int kq  = idx & 7;
            int gn  = nb + nd;
            float4 v = make_float4(0.f, 0.f, 0.f, 0.f);
            if (gn < N_NODES)
                v = *reinterpret_cast<const float4*>(&feat[(size_t)gn * IN_DIM + kc * 32 + kq * 4]);
            sA[kq * 4 + 0][nd] = v.x;
            sA[kq * 4 + 1][nd] = v.y;
            sA[kq * 4 + 2][nd] = v.z;
            sA[kq * 4 + 3][nd] = v.w;
        }
#pragma unroll
        for (int l = 0; l < 2; l++) {
            int idx = tid + l * 256;
            int kk = idx >> 4, c4 = idx & 15;
            float4 v = *reinterpret_cast<const float4*>(&w1[(kc * 32 + kk) * HID + c4 * 4]);
            *reinterpret_cast<float4*>(&sB[kk][c4 * 4]) = v;
        }
        __syncthreads();
#pragma unroll
        for (int kk = 0; kk < 32; kk++) {
            float4 b = *reinterpret_cast<float4*>(&sB[kk][tx * 4]);
            ull bb[4];
            bb[0] = pack2(b.x, b.x); bb[1] = pack2(b.y, b.y);
            bb[2] = pack2(b.z, b.z); bb[3] = pack2(b.w, b.w);
            longlong2 aA = *reinterpret_cast<longlong2*>(&sA[kk][ty * 8]);
            longlong2 aB = *reinterpret_cast<longlong2*>(&sA[kk][ty * 8 + 4]);
            ull ap[4] = {(ull)aA.x, (ull)aA.y, (ull)aB.x, (ull)aB.y};
#pragma unroll
            for (int p = 0; p < 4; p++) {
                fma2(acc2[p][0], ap[p], bb[0]);
                fma2(acc2[p][1], ap[p], bb[1]);
                fma2(acc2[p][2], ap[p], bb[2]);
                fma2(acc2[p][3], ap[p], bb[3]);
            }
        }
        __syncthreads();
    }
#pragma unroll
    for (int p = 0; p < 4; p++) {
        float lo[4], hi[4];
#pragma unroll
        for (int c = 0; c < 4; c++) unpack2(acc2[p][c], lo[c], hi[c]);
        int gn0 = nb + ty * 8 + 2 * p;
        int gn1 = gn0 + 1;
        if (gn0 < N_NODES)
            *reinterpret_cast<float4*>(&g_t[(size_t)gn0 * HID + tx * 4]) =
                make_float4(lo[0], lo[1], lo[2], lo[3]);
        if (gn1 < N_NODES)
            *reinterpret_cast<float4*>(&g_t[(size_t)gn1 * HID + tx * 4]) =
                make_float4(hi[0], hi[1], hi[2], hi[3]);
    }
}

// ---------------- scale: g_t[row] *= norm[row] (overlaps k_fill) ----------------
__global__ __launch_bounds__(256) void k_scale() {
    int idx = blockIdx.x * blockDim.x + threadIdx.x;   // < N*HID/4
    if (idx >= N_NODES * HID / 4) return;
    int row = idx >> 4;
    float nm = g_norm[row];
    float4 v = *reinterpret_cast<float4*>(&g_t[(size_t)idx * 4]);
    v.x *= nm; v.y *= nm; v.z *= nm; v.w *= nm;
    *reinterpret_cast<float4*>(&g_t[(size_t)idx * 4]) = v;
}

// ---------------- gathers --------------------------------------------------------
template<int FIN>
__global__ __launch_bounds__(256) void k_gather(const float* __restrict__ sbuf,
                                                float* __restrict__ obuf,
                                                uint32_t k0, uint32_t k1) {
    if (FIN == 0 && blockIdx.x == 0 && threadIdx.x < HID)
        g_colsum[threadIdx.x] = 0.f;
    int w = (blockIdx.x * blockDim.x + threadIdx.x) >> 5;
    if (w >= N_NODES) return;
    int lane = threadIdx.x & 31;
    if (FIN == 0) {
        ull m = gen_mask_word(k0, k1, w);
        if (lane == 0) g_mask2[w] = m;
    }
    int beg = g_rowptr[w], end = g_rowptr[w + 1];
    const char* sb = reinterpret_cast<const char*>(sbuf) + lane * 8;
    ull acc0 = *reinterpret_cast<const ull*>(sb + (size_t)w * ROW_BYTES);  // self loop
    ull acc1 = 0ull;
    for (int base = beg; base < end; base += 32) {
        int j = base + lane;
        int off = (j < end) ? g_csr[j] : 0;
        int cnt = min(32, end - base);
#pragma unroll 8
        for (int t = 0; t < cnt; t++) {
            int so = __shfl_sync(0xffffffffu, off, t);
            ull v = *reinterpret_cast<const ull*>(sb + (unsigned)so);
            if (t & 1) add2(acc1, v); else add2(acc0, v);
        }
    }
    add2(acc0, acc1);
    float ax, ay;
    unpack2(acc0, ax, ay);
    if (FIN == 1) {
        float nw = g_norm[w];
        ax = fmaxf(ax * nw, 0.f);
        ay = fmaxf(ay * nw, 0.f);
        uint32_t idx = (uint32_t)w * HID + (uint32_t)(lane * 2);
        ax = drop_keep(k0, k1, idx)     ? 2.f * ax : 0.f;
        ay = drop_keep(k0, k1, idx + 1) ? 2.f * ay : 0.f;
        ax *= nw; ay *= nw;
    }
    *reinterpret_cast<float2*>(&obuf[(size_t)w * HID + lane * 2]) = make_float2(ax, ay);
}

// ---------------- fin2 (64 nodes/block, FFMA2, mask from g_mask2) ----------------
__global__ __launch_bounds__(512) void k_fin2(const float* __restrict__ w2) {
    __shared__ float sW[64 * 64];
    __shared__ float sIn[64 * 64];
    __shared__ float sPart[8][65];
    int tid = threadIdx.x;
    int nb = blockIdx.x * 64;
#pragma unroll
    for (int l = 0; l < 2; l++) {
        int i = (tid + l * 512) * 4;
        *reinterpret_cast<float4*>(&sW[i]) = *reinterpret_cast<const float4*>(&w2[i]);
    }
#pragma unroll
    for (int l = 0; l < 2; l++) {
        int i = (tid + l * 512) * 4;
        int n = i >> 6;
        float4 v = make_float4(0.f, 0.f, 0.f, 0.f);
        if (nb + n < N_NODES)
            v = *reinterpret_cast<const float4*>(&g_agg2[(size_t)(nb + n) * HID + (i & 63)]);
        *reinterpret_cast<float4*>(&sIn[i]) = v;
    }
    __syncthreads();
    int n  = tid >> 3;
    int cg = tid & 7;
    ull acc2[4] = {0ull, 0ull, 0ull, 0ull};
    const float* a = &sIn[n * 64];
#pragma unroll
    for (int k = 0; k < 64; k++) {
        ull av2 = pack2(a[k], a[k]);
        const ull* bp = reinterpret_cast<const ull*>(&sW[k * 64 + cg * 8]);
        fma2(acc2[0], av2, bp[0]);
        fma2(acc2[1], av2, bp[1]);
        fma2(acc2[2], av2, bp[2]);
        fma2(acc2[3], av2, bp[3]);
    }
    float accf[8];
#pragma unroll
    for (int j = 0; j < 4; j++) unpack2(acc2[j], accf[2 * j], accf[2 * j + 1]);
    int gn = nb + n;
    bool ok = (gn < N_NODES);
    float nm = ok ? g_norm[gn] : 0.f;
    ull m = ok ? (g_mask2[gn] >> (cg * 8)) : 0ull;
    float vout[8];
#pragma unroll
    for (int c = 0; c < 8; c++) {
        float v = fmaxf(accf[c] * nm, 0.f);
        v = ((m >> c) & 1ull) ? 2.f * v : 0.f;
        vout[c] = v;
    }
    if (ok) {
        *reinterpret_cast<float4*>(&g_h2[(size_t)gn * HID + cg * 8]) =
            make_float4(vout[0], vout[1], vout[2], vout[3]);
        *reinterpret_cast<float4*>(&g_h2[(size_t)gn * HID + cg * 8 + 4]) =
            make_float4(vout[4], vout[5], vout[6], vout[7]);
    }
    __syncthreads();
    float* sOut = sW;
#pragma unroll
    for (int c = 0; c < 8; c++)
        sOut[n * 64 + cg * 8 + c] = ok ? vout[c] : 0.f;
    __syncthreads();
    {
        int c = tid & 63, chunk = tid >> 6;
        float s = 0.f;
#pragma unroll
        for (int i = 0; i < 8; i++) s += sOut[(chunk * 8 + i) * 64 + c];
        sPart[chunk][c] = s;
    }
    __syncthreads();
    if (tid < 64) {
        float s = 0.f;
#pragma unroll
        for (int i = 0; i < 8; i++) s += sPart[i][tid];
        atomicAdd(&g_colsum[tid], s);
    }
}

// ---------------- final: conv + radius + clip + cleanup ---------------------------
__global__ void k_final(const float* __restrict__ cw, const float* __restrict__ cb,
                        const float* __restrict__ ref, float* __restrict__ out) {
    __shared__ float sO[CONVOUT];
    __shared__ float m[64];
    int tid = threadIdx.x;
    if (tid < 64) m[tid] = g_colsum[tid] * (1.f / (float)N_NODES);
    __syncthreads();
    if (tid < CONVOUT) {
        int o = tid / 62, jj = tid % 62;
        sO[tid] = cw[o * 3 + 0] * m[jj] + cw[o * 3 + 1] * m[jj + 1]
                + cw[o * 3 + 2] * m[jj + 2] + cb[o];
    }
    __syncthreads();
    int lane = tid & 31, warp = tid >> 5;
    int node = blockIdx.x * 8 + warp;
    float w00 = cw[0], w01 = cw[1], w02 = cw[2];
    float w10 = cw[3], w11 = cw[4], w12 = cw[5];
    float b0 = cb[0], b1 = cb[1];
    const float* h = &g_h2[(size_t)node * HID];
    float acc = 0.f;
#pragma unroll
    for (int l = 0; l < 4; l++) {
        int j = lane * 4 + l;
        if (j < CONVOUT) {
            float y;
            if (j < 62) y = w00 * h[j] + w01 * h[j + 1] + w02 * h[j + 2] + b0;
            else { int jj = j - 62; y = w10 * h[jj] + w11 * h[jj + 1] + w12 * h[jj + 2] + b1; }
            float d = y - sO[j] + 1e-6f;
            acc += d * d;
        }
    }
#pragma unroll
    for (int o = 16; o; o >>= 1) acc += __shfl_xor_sync(0xffffffffu, acc, o);
    if (lane == 0) {
        float r = sqrtf(acc);
        out[node] = fminf(fmaxf(r - ref[0], 1e-4f), 0.9999f);
    }
    if (blockIdx.x == 0 && tid == 0) out[N_NODES] = ref[0];
    int gid = blockIdx.x * blockDim.x + tid;
    if (gid < N_NODES) g_deg[gid] = 0;
    if (gid == 0) { g_arrive1 = 0; g_arrive2 = 0; g_flag = 0; }
}

// ---------------- launch (fork/join: prep on s0, gemm+scale on s2) ---------------
extern "C" void kernel_launch(void* const* d_in, const int* in_sizes, int n_in,
                              void* d_out, int out_size) {
    const float* feat = (const float*)d_in[0];
    const float* w1   = (const float*)d_in[1];
    const float* w2   = (const float*)d_in[2];
    const float* cw   = (const float*)d_in[3];
    const float* cb   = (const float*)d_in[4];
    const float* ref  = (const float*)d_in[5];
    const int*   src  = (const int*)d_in[6];
    const int*   dst  = (const int*)d_in[7];
    float* out = (float*)d_out;

    uint32_t ka0 = 0, ka1 = 0, kb0 = 0, kb1 = 1;
    tf2x32(0u, 42u, ka0, ka1);
    tf2x32(0u, 42u, kb0, kb1);

    float* t_ptr;   cudaGetSymbolAddress((void**)&t_ptr, g_t);
    float* h1_ptr;  cudaGetSymbolAddress((void**)&h1_ptr, g_h1);
    float* a2_ptr;  cudaGetSymbolAddress((void**)&a2_ptr, g_agg2);

    static cudaStream_t s2 = nullptr;
    static cudaEvent_t evF = nullptr, evN = nullptr, evJ = nullptr;
    if (s2 == nullptr) {
        cudaStreamCreateWithFlags(&s2, cudaStreamNonBlocking);
        cudaEventCreateWithFlags(&evF, cudaEventDisableTiming);
        cudaEventCreateWithFlags(&evN, cudaEventDisableTiming);
        cudaEventCreateWithFlags(&evJ, cudaEventDisableTiming);
    }

    cudaEventRecord(evF, 0);                    // fork point
    cudaStreamWaitEvent(s2, evF, 0);

    k_degscan<<<NSCANB, SCAN_B>>>(dst);                          // s0  [#0]
    cudaEventRecord(evN, 0);                                     // norm ready

    k_gemm1<<<(N_NODES + 127) / 128, 256, 0, s2>>>(feat, w1);    // s2  [#1]
    cudaStreamWaitEvent(s2, evN, 0);
    k_scale<<<(N_NODES * HID / 4 + 255) / 256, 256, 0, s2>>>();  // s2  [#2]
    cudaEventRecord(evJ, s2);

    k_fill<<<(N_EDGES + 255) / 256, 256>>>(src, dst);            // s0  [#3] <- ncu slot
    cudaStreamWaitEvent(0, evJ, 0);                              // join

    k_gather<1><<<(N_NODES * 32 + 255) / 256, 256>>>(t_ptr, h1_ptr, ka0, ka1);  // [#4]
    k_gather<0><<<(N_NODES * 32 + 255) / 256, 256>>>(h1_ptr, a2_ptr, kb0, kb1); // [#5]
    k_fin2<<<(N_NODES + 63) / 64, 512>>>(w2);                                   // [#6]
    k_final<<<N_NODES / 8, 256>>>(cw, cb, ref, out);                            // [#7]
}